// round 14
// baseline (speedup 1.0000x reference)
#include <cuda_runtime.h>
#include <cstdint>

#define N_BOX 9216
#define NW 144            // 9216/64 mask words per row
#define NWIN 18           // 18 windows of 512 boxes (8 words) each

// ---------------- device scratch (no allocations allowed) ----------------
__device__ float g_x[512 * 1024];                      // conv output (relu'd)
__device__ float g_hpart[4 * 54 * 1024];               // head partial sums (4 c-chunks)
__device__ float4 g_boxes[N_BOX];                      // clipped proposals, original order
__device__ float4 g_sbox[N_BOX];                       // sorted boxes
__device__ float  g_sarea[N_BOX];
__device__ int    g_sorder[N_BOX];
__device__ int    g_rank[N_BOX];
__device__ unsigned long long g_keys[N_BOX];
__device__ unsigned long long g_mask[(size_t)N_BOX * NW];  // 10.6 MB suppression bitmask
__device__ unsigned long long g_keepw[NW];

// ---------------- packed f32x2 helpers (lanes are independent fp32 FMAs) ----------------
__device__ __forceinline__ unsigned long long pk2(float lo, float hi) {
    unsigned long long r;
    asm("mov.b64 %0, {%1, %2};" : "=l"(r) : "f"(lo), "f"(hi));
    return r;
}
__device__ __forceinline__ void fma2(unsigned long long& d, unsigned long long a,
                                     unsigned long long b) {
    asm("fma.rn.f32x2 %0, %1, %2, %0;" : "+l"(d) : "l"(a), "l"(b));
}
__device__ __forceinline__ void unpk(unsigned long long v, float& lo, float& hi) {
    asm("mov.b64 {%0, %1}, %2;" : "=f"(lo), "=f"(hi) : "l"(v));
}

// ---------------- 3x3 conv + bias + relu: FFMA2, R9 structure ----------------
// grid (32 oc-tiles, 8 row-tiles), 256 threads; 16 oc x 4 rows x 32 cols/block.
// Pixel pairs (p0,p1),(p2,p3) in f32x2 accumulators. Per-accumulator tap order
// (cc asc; w0..w8 row-major) identical to R9/R12 -> bit-identical results.
__global__ __launch_bounds__(256) void k_conv(const float* __restrict__ feat,
                                              const float* __restrict__ W,
                                              const float* __restrict__ B) {
    __shared__ __align__(16) float sf[8 * 240];        // 8 ch x (6 rows x 40)
    __shared__ unsigned long long swd[16 * 72];        // dup (w,w) pairs, 9.2 KB
    const int tid = threadIdx.x;
    const int oc0 = blockIdx.x * 16;
    const int y0 = blockIdx.y * 4;
    const int xg = tid & 7, rr = (tid >> 3) & 3, og = tid >> 5;
    const int x0 = xg * 4;

    // zero smem once: halos + edge-invalid rows + pads stay zero forever
    for (int i = tid; i < 8 * 240; i += 256) sf[i] = 0.f;

    // --- loop-invariant staging slots ---
    int fga[2], fsa[2];
    bool fv[2];
#pragma unroll
    for (int k = 0; k < 2; k++) {
        int idx = tid + k * 256;
        bool live = idx < 384;
        int cc = idx / 48, r6 = (idx >> 3) % 6, q = idx & 7;
        int gy = y0 + r6 - 1;
        fv[k] = live && ((unsigned)gy < 32u);
        fga[k] = cc * 1024 + gy * 32 + q * 4;
        fsa[k] = cc * 240 + r6 * 40 + 1 + q * 4;
    }
    int wga[5], wsa[5];
    bool wv[5];
#pragma unroll
    for (int k = 0; k < 5; k++) {
        int i = tid + k * 256;
        wv[k] = i < 1152;
        int o = i / 72, rem = i - o * 72;
        wga[k] = (oc0 + o) * 2304 + rem;
        wsa[k] = o * 72 + rem;
    }

    float4 pf[2];
    float pw[5];
#pragma unroll
    for (int k = 0; k < 2; k++)
        pf[k] = fv[k] ? *(const float4*)(feat + fga[k]) : make_float4(0.f, 0.f, 0.f, 0.f);
#pragma unroll
    for (int k = 0; k < 5; k++)
        pw[k] = wv[k] ? W[wga[k]] : 0.f;

    unsigned long long acc[2][2];   // [o2][pixel-pair]; 0ull == (0.f, 0.f)
#pragma unroll
    for (int a = 0; a < 2; a++)
#pragma unroll
        for (int b = 0; b < 2; b++) acc[a][b] = 0ull;

    __syncthreads();   // orders the zero-fill before first STS round

    for (int c0 = 0; c0 < 256; c0 += 8) {
        // store staged regs to smem (weights duplicated into f32x2 pairs)
#pragma unroll
        for (int k = 0; k < 2; k++)
            if (fv[k]) {
                float* s = &sf[fsa[k]];
                s[0] = pf[k].x; s[1] = pf[k].y; s[2] = pf[k].z; s[3] = pf[k].w;
            }
#pragma unroll
        for (int k = 0; k < 5; k++)
            if (wv[k]) swd[wsa[k]] = pk2(pw[k], pw[k]);
        __syncthreads();

        // prefetch next chunk (LDG hidden behind compute below)
        if (c0 + 8 < 256) {
#pragma unroll
            for (int k = 0; k < 2; k++) {
                fga[k] += 8 * 1024;
                if (fv[k]) pf[k] = *(const float4*)(feat + fga[k]);
            }
#pragma unroll
            for (int k = 0; k < 5; k++) {
                wga[k] += 72;
                if (wv[k]) pw[k] = W[wga[k]];
            }
        }

#pragma unroll
        for (int cc = 0; cc < 8; cc++) {
            // pairs P[dy] = {(f0,f1),(f1,f2),(f2,f3),(f3,f4),(f4,f5)}
            unsigned long long P[3][5];
#pragma unroll
            for (int dy = 0; dy < 3; dy++) {
                const float* frow = &sf[cc * 240 + (rr + dy) * 40 + x0];
                float4 a = *(const float4*)frow;        // LDS.128 (16B aligned)
                float2 b = *(const float2*)(frow + 4);  // LDS.64
                P[dy][0] = pk2(a.x, a.y);
                P[dy][1] = pk2(a.y, a.z);
                P[dy][2] = pk2(a.z, a.w);
                P[dy][3] = pk2(a.w, b.x);
                P[dy][4] = pk2(b.x, b.y);
            }
#pragma unroll
            for (int o2 = 0; o2 < 2; o2++) {
                const unsigned long long* wp = &swd[(og * 2 + o2) * 72 + cc * 9];
                unsigned long long a0 = acc[o2][0], a1 = acc[o2][1];
#pragma unroll
                for (int dy = 0; dy < 3; dy++) {
                    unsigned long long w0 = wp[3 * dy];
                    unsigned long long w1 = wp[3 * dy + 1];
                    unsigned long long w2 = wp[3 * dy + 2];
                    fma2(a0, P[dy][0], w0);   // p0,p1 += w*f[dy][p]
                    fma2(a0, P[dy][1], w1);
                    fma2(a0, P[dy][2], w2);
                    fma2(a1, P[dy][2], w0);   // p2,p3
                    fma2(a1, P[dy][3], w1);
                    fma2(a1, P[dy][4], w2);
                }
                acc[o2][0] = a0; acc[o2][1] = a1;
            }
        }
        __syncthreads();
    }

    const int y = y0 + rr;
#pragma unroll
    for (int o2 = 0; o2 < 2; o2++) {
        int oc = oc0 + og * 2 + o2;
        float b = B[oc];
#pragma unroll
        for (int pp = 0; pp < 2; pp++) {
            float lo, hi;
            unpk(acc[o2][pp], lo, hi);
            float v0 = lo + b, v1 = hi + b;
            int base = oc * 1024 + y * 32 + x0 + pp * 2;
            g_x[base] = v0 > 0.f ? v0 : 0.f;
            g_x[base + 1] = v1 > 0.f ? v1 : 0.f;
        }
    }
}

// ---------------- 1x1 heads (R9 frozen) ----------------
__global__ __launch_bounds__(256) void k_heads(const float* __restrict__ cw,
                                               const float* __restrict__ bw) {
    __shared__ float red[54][32];
    const int tid = threadIdx.x;
    const int lane = tid & 31, sub = tid >> 5;
    const int px = blockIdx.x * 32 + lane;
    const int q = blockIdx.y;

    float ac[18], ab[36];
#pragma unroll
    for (int o = 0; o < 18; o++) ac[o] = 0.f;
#pragma unroll
    for (int o = 0; o < 36; o++) ab[o] = 0.f;

    const int cbeg = q * 128 + sub * 16;
    for (int c = cbeg; c < cbeg + 16; c += 4) {
        float x0 = g_x[c * 1024 + px];
        float x1 = g_x[(c + 1) * 1024 + px];
        float x2 = g_x[(c + 2) * 1024 + px];
        float x3 = g_x[(c + 3) * 1024 + px];
#pragma unroll
        for (int o = 0; o < 18; o++) {
            float4 w = *(const float4*)(cw + o * 512 + c);
            ac[o] += w.x * x0 + w.y * x1 + w.z * x2 + w.w * x3;
        }
#pragma unroll
        for (int o = 0; o < 36; o++) {
            float4 w = *(const float4*)(bw + o * 512 + c);
            ab[o] += w.x * x0 + w.y * x1 + w.z * x2 + w.w * x3;
        }
    }

    for (int j = tid; j < 54 * 32; j += 256) (&red[0][0])[j] = 0.f;
    __syncthreads();
    for (int k = 0; k < 8; k++) {   // deterministic fixed-order sub accumulation
        if (sub == k) {
#pragma unroll
            for (int o = 0; o < 18; o++) red[o][lane] += ac[o];
#pragma unroll
            for (int o = 0; o < 36; o++) red[18 + o][lane] += ab[o];
        }
        __syncthreads();
    }
    for (int j = tid; j < 54 * 32; j += 256) {
        int o = j >> 5, p = j & 31;
        g_hpart[q * 55296 + o * 1024 + blockIdx.x * 32 + p] = red[o][p];
    }
}

// ---------------- head-sum helper: fixed-order 4-partial reduction ----------------
__device__ __forceinline__ float head_sum(int idx, float bias) {
    float v = bias;
    v += g_hpart[idx];
    v += g_hpart[55296 + idx];
    v += g_hpart[2 * 55296 + idx];
    v += g_hpart[3 * 55296 + idx];
    return v;
}

// ---------------- decode boxes + clip + keys + probs ----------------
__global__ void k_prop(float* __restrict__ out, const int* __restrict__ imgsz,
                       const float* __restrict__ cbv, const float* __restrict__ bbv) {
    int r = blockIdx.x * blockDim.x + threadIdx.x;
    if (r >= N_BOX) return;
    int isz = imgsz[0];
    float img = (float)isz;
    float strd = (float)(isz / 32);

    {   // probs: entries r and r+9216 of the 18432 prob outputs
        int o = r >> 10;
        float v = head_sum(r, cbv[o]);
        out[36864 + r] = 1.f / (1.f + expf(-v));
        int o2 = o + 9;
        float v2 = head_sum(r + 9216, cbv[o2]);
        out[36864 + 9216 + r] = 1.f / (1.f + expf(-v2));
    }

    int a = r >> 10, s = r & 1023;
    float logit = head_sum((2 * a + 1) * 1024 + s, cbv[2 * a + 1]);
    float score = 1.f / (1.f + expf(-logit));

    int c0 = r >> 8, s0 = (r & 255) << 2;
    float d[4];
#pragma unroll
    for (int k = 0; k < 4; k++)
        d[k] = head_sum((18 + c0) * 1024 + s0 + k, bbv[c0]);
    float dx = d[0], dyv = d[1], dw = d[2], dh = d[3];

    int sa = r / 9, aa = r - sa * 9;
    int ix = sa & 31, iy = sa >> 5;
    const float ratios[3] = {0.5f, 1.f, 2.f};
    const float scales[3] = {128.f, 256.f, 512.f};
    float ratio = ratios[aa / 3], scale = scales[aa % 3];
    float hr = sqrtf(ratio), wr = 1.f / hr;
    float w2 = rintf(0.5f * (wr * scale));
    float h2 = rintf(0.5f * (hr * scale));
    float shx = ix * strd, shy = iy * strd;
    float x1 = shx - w2, y1 = shy - h2, x2 = shx + w2, y2 = shy + h2;

    float w = x2 - x1, h = y2 - y1;
    float cx = x1 + 0.5f * w, cy = y1 + 0.5f * h;
    float pcx = dx * w + cx, pcy = dyv * h + cy;
    float pw = expf(dw) * w, ph = expf(dh) * h;
    float bx1 = pcx - 0.5f * pw, by1 = pcy - 0.5f * ph;
    float bx2 = pcx + 0.5f * pw, by2 = pcy + 0.5f * ph;
    bx1 = fminf(fmaxf(bx1, 0.f), img); by1 = fminf(fmaxf(by1, 0.f), img);
    bx2 = fminf(fmaxf(bx2, 0.f), img); by2 = fminf(fmaxf(by2, 0.f), img);

    g_boxes[r] = make_float4(bx1, by1, bx2, by2);
    unsigned int sb = __float_as_uint(score);
    g_keys[r] = ((unsigned long long)(~sb) << 32) | (unsigned int)r;
    g_rank[r] = 0;
}

// ---------------- rank by counting (frozen: grid (36,8)) ----------------
__global__ __launch_bounds__(256) void k_rank() {
    __shared__ unsigned long long sk[1152];
    const int tid = threadIdx.x;
    const int jbase = blockIdx.y * 1152;
    for (int j = tid; j < 1152; j += 256) sk[j] = g_keys[jbase + j];
    __syncthreads();
    const int i = blockIdx.x * 256 + tid;
    const unsigned long long ki = g_keys[i];
    int c0 = 0, c1 = 0, c2 = 0, c3 = 0, c4 = 0, c5 = 0, c6 = 0, c7 = 0;
#pragma unroll 2
    for (int j = 0; j < 1152; j += 8) {   // all lanes same addr -> LDS broadcast
        c0 += (sk[j]     < ki);
        c1 += (sk[j + 1] < ki);
        c2 += (sk[j + 2] < ki);
        c3 += (sk[j + 3] < ki);
        c4 += (sk[j + 4] < ki);
        c5 += (sk[j + 5] < ki);
        c6 += (sk[j + 6] < ki);
        c7 += (sk[j + 7] < ki);
    }
    atomicAdd(&g_rank[i], (c0 + c1 + c2 + c3) + (c4 + c5 + c6 + c7));
}

// ---------------- scatter into sorted order ----------------
__global__ void k_scatter() {
    int r = blockIdx.x * blockDim.x + threadIdx.x;
    if (r >= N_BOX) return;
    int rk = g_rank[r];
    g_sorder[rk] = r;
    float4 b = g_boxes[r];
    g_sbox[rk] = b;
    g_sarea[rk] = (b.z - b.x) * (b.w - b.y);
}

// ---------------- NMS bitmask: diag/off-diag specialized, 4 tiles per block ----------------
__global__ __launch_bounds__(256) void k_mask() {
    __shared__ float4 cbox[4][64];
    __shared__ float carea[4][64];
    const int t = threadIdx.x;
    const int sub = t >> 6, tt = t & 63;
    const int lin = blockIdx.x * 4 + sub;   // grid*4 == 10440 exactly

    int rb = (int)(NW + 0.5f - sqrtf((NW + 0.5f) * (NW + 0.5f) - 2.0f * (float)lin));
    while (rb > 0 && (rb * NW - rb * (rb - 1) / 2) > lin) rb--;
    while ((rb + 1) * NW - (rb + 1) * rb / 2 <= lin) rb++;
    const int cb = rb + (lin - (rb * NW - rb * (rb - 1) / 2));

    const int j0 = cb * 64;
    cbox[sub][tt] = g_sbox[j0 + tt];
    carea[sub][tt] = g_sarea[j0 + tt];
    __syncthreads();

    const int i = rb * 64 + tt;
    float4 bi = g_sbox[i];
    float ai = g_sarea[i];
    unsigned long long bits = 0;
    if (cb == rb) {
#pragma unroll 4
        for (int jj = 0; jj < 64; ++jj) {
            if (jj > tt) {
                float4 bj = cbox[sub][jj];
                float xx1 = fmaxf(bi.x, bj.x), yy1 = fmaxf(bi.y, bj.y);
                float xx2 = fminf(bi.z, bj.z), yy2 = fminf(bi.w, bj.w);
                float w = fmaxf(xx2 - xx1, 0.f), h = fmaxf(yy2 - yy1, 0.f);
                float inter = w * h;
                float iou = inter / (ai + carea[sub][jj] - inter + 1e-9f);
                if (iou > 0.3f) bits |= 1ull << jj;
            }
        }
    } else {
#pragma unroll 4
        for (int jj = 0; jj < 64; ++jj) {
            float4 bj = cbox[sub][jj];
            float xx1 = fmaxf(bi.x, bj.x), yy1 = fmaxf(bi.y, bj.y);
            float xx2 = fminf(bi.z, bj.z), yy2 = fminf(bi.w, bj.w);
            float w = fmaxf(xx2 - xx1, 0.f), h = fmaxf(yy2 - yy1, 0.f);
            float inter = w * h;
            float iou = inter / (ai + carea[sub][jj] - inter + 1e-9f);
            if (iou > 0.3f) bits |= 1ull << jj;
        }
    }
    g_mask[(size_t)i * NW + cb] = bits;
}

// ---------------- windowed greedy reduce: 18 iterations of 512 boxes ----------------
__global__ __launch_bounds__(1024) void k_reduce() {
    extern __shared__ unsigned long long loc[];     // [2][512][8] = 64 KB
    __shared__ unsigned long long remv[NW];
    __shared__ int s_kept[512];
    __shared__ int s_cnt;
    const int t = threadIdx.x;
    if (t < NW) remv[t] = 0;
#pragma unroll
    for (int k = 0; k < 4; k++) {                   // preload window 0 local words
        int idx = t + k * 1024;
        int L = idx >> 3, wl = idx & 7;
        loc[idx] = g_mask[(size_t)L * NW + wl];
    }
    __syncthreads();

    const int g = t / NW;            // group 0..6 (t < 1008)
    const int w = t - g * NW;

    for (int win = 0; win < NWIN; ++win) {
        const int cur = (win & 1) * 4096, nxt = 4096 - cur;
        if (win + 1 < NWIN) {        // prefetch next window (hidden behind greedy + OR)
#pragma unroll
            for (int k = 0; k < 4; k++) {
                int idx = t + k * 1024;
                int L = idx >> 3, wl = idx & 7;
                loc[nxt + idx] =
                    g_mask[(size_t)((win + 1) * 512 + L) * NW + (win + 1) * 8 + wl];
            }
        }
        if (t == 0) {
            unsigned long long aw[8], kw[8];
#pragma unroll
            for (int wl = 0; wl < 8; wl++) {
                aw[wl] = ~remv[win * 8 + wl];
                kw[wl] = 0;
            }
            int cnt = 0;
#pragma unroll
            for (int wl = 0; wl < 8; wl++) {
                unsigned long long avail = aw[wl];
                while (avail) {
                    int b = __ffsll((long long)avail) - 1;
                    int L = wl * 64 + b;
                    kw[wl] |= 1ull << b;
                    s_kept[cnt++] = L;
                    const unsigned long long* lp = &loc[cur + L * 8];
                    avail &= ~(lp[wl] | (1ull << b));
#pragma unroll
                    for (int w2 = 0; w2 < 8; w2++)
                        if (w2 > wl) aw[w2] &= ~lp[w2];
                }
            }
            s_cnt = cnt;
#pragma unroll
            for (int wl = 0; wl < 8; wl++) g_keepw[win * 8 + wl] = kw[wl];
        }
        __syncthreads();
        const int cnt = s_cnt;
        if (g < 7 && w >= (win + 1) * 8 && cnt > g) {
            unsigned long long acc = 0;
            for (int k = g; k < cnt; k += 7)
                acc |= g_mask[(size_t)(win * 512 + s_kept[k]) * NW + w];
            if (acc) atomicOr(&remv[w], acc);
        }
        __syncthreads();
    }
}

// ---------------- finalize (separate kernel) ----------------
__global__ void k_final(float* __restrict__ out) {
    int r = blockIdx.x * blockDim.x + threadIdx.x;
    if (r >= N_BOX) return;
    int orig = g_sorder[r];
    float m = (float)((g_keepw[r >> 6] >> (r & 63)) & 1ull);
    float4 b = g_boxes[orig];
    out[4 * orig + 0] = b.x * m;
    out[4 * orig + 1] = b.y * m;
    out[4 * orig + 2] = b.z * m;
    out[4 * orig + 3] = b.w * m;
    out[55296 + orig] = m;
}

// ---------------- launcher ----------------
extern "C" void kernel_launch(void* const* d_in, const int* in_sizes, int n_in,
                              void* d_out, int out_size) {
    const float* feat   = (const float*)d_in[0];
    const int*   imgsz  = (const int*)d_in[1];
    const float* conv_w = (const float*)d_in[2];
    const float* conv_b = (const float*)d_in[3];
    const float* cls_w  = (const float*)d_in[4];
    const float* cls_b  = (const float*)d_in[5];
    const float* bbox_w = (const float*)d_in[6];
    const float* bbox_b = (const float*)d_in[7];
    float* out = (float*)d_out;

    cudaFuncSetAttribute(k_reduce, cudaFuncAttributeMaxDynamicSharedMemorySize, 65536);

    k_conv<<<dim3(32, 8), 256>>>(feat, conv_w, conv_b);
    k_heads<<<dim3(32, 4), 256>>>(cls_w, bbox_w);
    k_prop<<<36, 256>>>(out, imgsz, cls_b, bbox_b);
    k_rank<<<dim3(36, 8), 256>>>();
    k_scatter<<<36, 256>>>();
    k_mask<<<2610, 256>>>();
    k_reduce<<<1, 1024, 65536>>>();
    k_final<<<36, 256>>>(out);
}

// round 15
// speedup vs baseline: 1.0982x; 1.0982x over previous
#include <cuda_runtime.h>
#include <cstdint>

#define N_BOX 9216
#define NW 144            // 9216/64 mask words per row
#define NWIN 12           // 12 windows of 768 boxes (12 words) each
#define WB 768            // boxes per window
#define WW 12             // mask words per window

// ---------------- device scratch (no allocations allowed) ----------------
__device__ float g_x[512 * 1024];                      // conv output (relu'd)
__device__ float g_hpart[4 * 54 * 1024];               // head partial sums (4 c-chunks)
__device__ float4 g_boxes[N_BOX];                      // clipped proposals, original order
__device__ float4 g_sbox[N_BOX];                       // sorted boxes
__device__ float  g_sarea[N_BOX];
__device__ int    g_sorder[N_BOX];
__device__ int    g_rank[N_BOX];
__device__ unsigned long long g_keys[N_BOX];
__device__ unsigned long long g_mask[(size_t)N_BOX * NW];  // 10.6 MB suppression bitmask
__device__ unsigned long long g_keepw[NW];

// ---------------- 3x3 conv + bias + relu (R9/R12 frozen — FFMA rt=2 wall) ----------------
__global__ __launch_bounds__(256) void k_conv(const float* __restrict__ feat,
                                              const float* __restrict__ W,
                                              const float* __restrict__ B) {
    __shared__ float sf[8 * 222];    // 8 ch x (6 rows x 37)
    __shared__ float sw[16 * 72];    // 16 oc x 72 taps per chunk
    const int tid = threadIdx.x;
    const int oc0 = blockIdx.x * 16;
    const int y0 = blockIdx.y * 4;
    const int xg = tid & 7, rr = (tid >> 3) & 3, og = tid >> 5;
    const int x0 = xg * 4;

    for (int i = tid; i < 8 * 222; i += 256) sf[i] = 0.f;

    int fga[2], fsa[2];
    bool fv[2];
#pragma unroll
    for (int k = 0; k < 2; k++) {
        int idx = tid + k * 256;
        bool live = idx < 384;
        int cc = idx / 48, r6 = (idx >> 3) % 6, q = idx & 7;
        int gy = y0 + r6 - 1;
        fv[k] = live && ((unsigned)gy < 32u);
        fga[k] = cc * 1024 + gy * 32 + q * 4;
        fsa[k] = cc * 222 + r6 * 37 + 1 + q * 4;
    }
    int wga[5], wsa[5];
    bool wv[5];
#pragma unroll
    for (int k = 0; k < 5; k++) {
        int i = tid + k * 256;
        wv[k] = i < 1152;
        int o = i / 72, rem = i - o * 72;
        wga[k] = (oc0 + o) * 2304 + rem;
        wsa[k] = o * 72 + rem;
    }

    float4 pf[2];
    float pw[5];
#pragma unroll
    for (int k = 0; k < 2; k++)
        pf[k] = fv[k] ? *(const float4*)(feat + fga[k]) : make_float4(0.f, 0.f, 0.f, 0.f);
#pragma unroll
    for (int k = 0; k < 5; k++)
        pw[k] = wv[k] ? W[wga[k]] : 0.f;

    float acc[2][4];
#pragma unroll
    for (int a = 0; a < 2; a++)
#pragma unroll
        for (int b = 0; b < 4; b++) acc[a][b] = 0.f;

    __syncthreads();

    for (int c0 = 0; c0 < 256; c0 += 8) {
#pragma unroll
        for (int k = 0; k < 2; k++)
            if (fv[k]) {
                float* s = &sf[fsa[k]];
                s[0] = pf[k].x; s[1] = pf[k].y; s[2] = pf[k].z; s[3] = pf[k].w;
            }
#pragma unroll
        for (int k = 0; k < 5; k++)
            if (wv[k]) sw[wsa[k]] = pw[k];
        __syncthreads();

        if (c0 + 8 < 256) {
#pragma unroll
            for (int k = 0; k < 2; k++) {
                fga[k] += 8 * 1024;
                if (fv[k]) pf[k] = *(const float4*)(feat + fga[k]);
            }
#pragma unroll
            for (int k = 0; k < 5; k++) {
                wga[k] += 72;
                if (wv[k]) pw[k] = W[wga[k]];
            }
        }

#pragma unroll
        for (int cc = 0; cc < 8; cc++) {
            float f[3][6];
#pragma unroll
            for (int dy = 0; dy < 3; dy++)
#pragma unroll
                for (int dx = 0; dx < 6; dx++)
                    f[dy][dx] = sf[cc * 222 + (rr + dy) * 37 + x0 + dx];
#pragma unroll
            for (int o2 = 0; o2 < 2; o2++) {
                const float* wp = &sw[(og * 2 + o2) * 72 + cc * 9];
                float w0 = wp[0], w1 = wp[1], w2 = wp[2], w3 = wp[3], w4 = wp[4];
                float w5 = wp[5], w6 = wp[6], w7 = wp[7], w8 = wp[8];
#pragma unroll
                for (int p = 0; p < 4; p++) {
                    float s = acc[o2][p];
                    s += w0 * f[0][p]; s += w1 * f[0][p + 1]; s += w2 * f[0][p + 2];
                    s += w3 * f[1][p]; s += w4 * f[1][p + 1]; s += w5 * f[1][p + 2];
                    s += w6 * f[2][p]; s += w7 * f[2][p + 1]; s += w8 * f[2][p + 2];
                    acc[o2][p] = s;
                }
            }
        }
        __syncthreads();
    }

    const int y = y0 + rr;
#pragma unroll
    for (int o2 = 0; o2 < 2; o2++) {
        int oc = oc0 + og * 2 + o2;
        float b = B[oc];
#pragma unroll
        for (int p = 0; p < 4; p++) {
            float v = acc[o2][p] + b;
            g_x[oc * 1024 + y * 32 + x0 + p] = v > 0.f ? v : 0.f;
        }
    }
}

// ---------------- 1x1 heads (R9 frozen) ----------------
__global__ __launch_bounds__(256) void k_heads(const float* __restrict__ cw,
                                               const float* __restrict__ bw) {
    __shared__ float red[54][32];
    const int tid = threadIdx.x;
    const int lane = tid & 31, sub = tid >> 5;
    const int px = blockIdx.x * 32 + lane;
    const int q = blockIdx.y;

    float ac[18], ab[36];
#pragma unroll
    for (int o = 0; o < 18; o++) ac[o] = 0.f;
#pragma unroll
    for (int o = 0; o < 36; o++) ab[o] = 0.f;

    const int cbeg = q * 128 + sub * 16;
    for (int c = cbeg; c < cbeg + 16; c += 4) {
        float x0 = g_x[c * 1024 + px];
        float x1 = g_x[(c + 1) * 1024 + px];
        float x2 = g_x[(c + 2) * 1024 + px];
        float x3 = g_x[(c + 3) * 1024 + px];
#pragma unroll
        for (int o = 0; o < 18; o++) {
            float4 w = *(const float4*)(cw + o * 512 + c);
            ac[o] += w.x * x0 + w.y * x1 + w.z * x2 + w.w * x3;
        }
#pragma unroll
        for (int o = 0; o < 36; o++) {
            float4 w = *(const float4*)(bw + o * 512 + c);
            ab[o] += w.x * x0 + w.y * x1 + w.z * x2 + w.w * x3;
        }
    }

    for (int j = tid; j < 54 * 32; j += 256) (&red[0][0])[j] = 0.f;
    __syncthreads();
    for (int k = 0; k < 8; k++) {   // deterministic fixed-order sub accumulation
        if (sub == k) {
#pragma unroll
            for (int o = 0; o < 18; o++) red[o][lane] += ac[o];
#pragma unroll
            for (int o = 0; o < 36; o++) red[18 + o][lane] += ab[o];
        }
        __syncthreads();
    }
    for (int j = tid; j < 54 * 32; j += 256) {
        int o = j >> 5, p = j & 31;
        g_hpart[q * 55296 + o * 1024 + blockIdx.x * 32 + p] = red[o][p];
    }
}

// ---------------- head-sum helper: fixed-order 4-partial reduction ----------------
__device__ __forceinline__ float head_sum(int idx, float bias) {
    float v = bias;
    v += g_hpart[idx];
    v += g_hpart[55296 + idx];
    v += g_hpart[2 * 55296 + idx];
    v += g_hpart[3 * 55296 + idx];
    return v;
}

// ---------------- decode boxes + clip + keys + probs ----------------
__global__ void k_prop(float* __restrict__ out, const int* __restrict__ imgsz,
                       const float* __restrict__ cbv, const float* __restrict__ bbv) {
    int r = blockIdx.x * blockDim.x + threadIdx.x;
    if (r >= N_BOX) return;
    int isz = imgsz[0];
    float img = (float)isz;
    float strd = (float)(isz / 32);

    {   // probs: entries r and r+9216 of the 18432 prob outputs
        int o = r >> 10;
        float v = head_sum(r, cbv[o]);
        out[36864 + r] = 1.f / (1.f + expf(-v));
        int o2 = o + 9;
        float v2 = head_sum(r + 9216, cbv[o2]);
        out[36864 + 9216 + r] = 1.f / (1.f + expf(-v2));
    }

    int a = r >> 10, s = r & 1023;
    float logit = head_sum((2 * a + 1) * 1024 + s, cbv[2 * a + 1]);
    float score = 1.f / (1.f + expf(-logit));

    int c0 = r >> 8, s0 = (r & 255) << 2;
    float d[4];
#pragma unroll
    for (int k = 0; k < 4; k++)
        d[k] = head_sum((18 + c0) * 1024 + s0 + k, bbv[c0]);
    float dx = d[0], dyv = d[1], dw = d[2], dh = d[3];

    int sa = r / 9, aa = r - sa * 9;
    int ix = sa & 31, iy = sa >> 5;
    const float ratios[3] = {0.5f, 1.f, 2.f};
    const float scales[3] = {128.f, 256.f, 512.f};
    float ratio = ratios[aa / 3], scale = scales[aa % 3];
    float hr = sqrtf(ratio), wr = 1.f / hr;
    float w2 = rintf(0.5f * (wr * scale));
    float h2 = rintf(0.5f * (hr * scale));
    float shx = ix * strd, shy = iy * strd;
    float x1 = shx - w2, y1 = shy - h2, x2 = shx + w2, y2 = shy + h2;

    float w = x2 - x1, h = y2 - y1;
    float cx = x1 + 0.5f * w, cy = y1 + 0.5f * h;
    float pcx = dx * w + cx, pcy = dyv * h + cy;
    float pw = expf(dw) * w, ph = expf(dh) * h;
    float bx1 = pcx - 0.5f * pw, by1 = pcy - 0.5f * ph;
    float bx2 = pcx + 0.5f * pw, by2 = pcy + 0.5f * ph;
    bx1 = fminf(fmaxf(bx1, 0.f), img); by1 = fminf(fmaxf(by1, 0.f), img);
    bx2 = fminf(fmaxf(bx2, 0.f), img); by2 = fminf(fmaxf(by2, 0.f), img);

    g_boxes[r] = make_float4(bx1, by1, bx2, by2);
    unsigned int sb = __float_as_uint(score);
    g_keys[r] = ((unsigned long long)(~sb) << 32) | (unsigned int)r;
    g_rank[r] = 0;
}

// ---------------- rank by counting (frozen: grid (36,8)) ----------------
__global__ __launch_bounds__(256) void k_rank() {
    __shared__ unsigned long long sk[1152];
    const int tid = threadIdx.x;
    const int jbase = blockIdx.y * 1152;
    for (int j = tid; j < 1152; j += 256) sk[j] = g_keys[jbase + j];
    __syncthreads();
    const int i = blockIdx.x * 256 + tid;
    const unsigned long long ki = g_keys[i];
    int c0 = 0, c1 = 0, c2 = 0, c3 = 0, c4 = 0, c5 = 0, c6 = 0, c7 = 0;
#pragma unroll 2
    for (int j = 0; j < 1152; j += 8) {   // all lanes same addr -> LDS broadcast
        c0 += (sk[j]     < ki);
        c1 += (sk[j + 1] < ki);
        c2 += (sk[j + 2] < ki);
        c3 += (sk[j + 3] < ki);
        c4 += (sk[j + 4] < ki);
        c5 += (sk[j + 5] < ki);
        c6 += (sk[j + 6] < ki);
        c7 += (sk[j + 7] < ki);
    }
    atomicAdd(&g_rank[i], (c0 + c1 + c2 + c3) + (c4 + c5 + c6 + c7));
}

// ---------------- scatter into sorted order ----------------
__global__ void k_scatter() {
    int r = blockIdx.x * blockDim.x + threadIdx.x;
    if (r >= N_BOX) return;
    int rk = g_rank[r];
    g_sorder[rk] = r;
    float4 b = g_boxes[r];
    g_sbox[rk] = b;
    g_sarea[rk] = (b.z - b.x) * (b.w - b.y);
}

// ---------------- NMS bitmask: diag/off-diag specialized, 4 tiles per block ----------------
__global__ __launch_bounds__(256) void k_mask() {
    __shared__ float4 cbox[4][64];
    __shared__ float carea[4][64];
    const int t = threadIdx.x;
    const int sub = t >> 6, tt = t & 63;
    const int lin = blockIdx.x * 4 + sub;   // grid*4 == 10440 exactly

    int rb = (int)(NW + 0.5f - sqrtf((NW + 0.5f) * (NW + 0.5f) - 2.0f * (float)lin));
    while (rb > 0 && (rb * NW - rb * (rb - 1) / 2) > lin) rb--;
    while ((rb + 1) * NW - (rb + 1) * rb / 2 <= lin) rb++;
    const int cb = rb + (lin - (rb * NW - rb * (rb - 1) / 2));

    const int j0 = cb * 64;
    cbox[sub][tt] = g_sbox[j0 + tt];
    carea[sub][tt] = g_sarea[j0 + tt];
    __syncthreads();

    const int i = rb * 64 + tt;
    float4 bi = g_sbox[i];
    float ai = g_sarea[i];
    unsigned long long bits = 0;
    if (cb == rb) {
#pragma unroll 4
        for (int jj = 0; jj < 64; ++jj) {
            if (jj > tt) {
                float4 bj = cbox[sub][jj];
                float xx1 = fmaxf(bi.x, bj.x), yy1 = fmaxf(bi.y, bj.y);
                float xx2 = fminf(bi.z, bj.z), yy2 = fminf(bi.w, bj.w);
                float w = fmaxf(xx2 - xx1, 0.f), h = fmaxf(yy2 - yy1, 0.f);
                float inter = w * h;
                float iou = inter / (ai + carea[sub][jj] - inter + 1e-9f);
                if (iou > 0.3f) bits |= 1ull << jj;
            }
        }
    } else {
#pragma unroll 4
        for (int jj = 0; jj < 64; ++jj) {
            float4 bj = cbox[sub][jj];
            float xx1 = fmaxf(bi.x, bj.x), yy1 = fmaxf(bi.y, bj.y);
            float xx2 = fminf(bi.z, bj.z), yy2 = fminf(bi.w, bj.w);
            float w = fmaxf(xx2 - xx1, 0.f), h = fmaxf(yy2 - yy1, 0.f);
            float inter = w * h;
            float iou = inter / (ai + carea[sub][jj] - inter + 1e-9f);
            if (iou > 0.3f) bits |= 1ull << jj;
        }
    }
    g_mask[(size_t)i * NW + cb] = bits;
}

// ---------------- windowed greedy reduce: 12 iterations of 768 boxes ----------------
// loc double buffer: 2 x (768 rows x 12 window-local words) = 144 KB dynamic smem.
// Preload/prefetch = exactly 9 words/thread (9216 = 9*1024).
__global__ __launch_bounds__(1024) void k_reduce() {
    extern __shared__ unsigned long long loc[];
    __shared__ unsigned long long remv[NW];
    __shared__ int s_kept[WB];
    __shared__ int s_cnt;
    const int t = threadIdx.x;
    if (t < NW) remv[t] = 0;
#pragma unroll
    for (int k = 0; k < 9; k++) {                   // preload window 0 local words
        int idx = t + k * 1024;
        int L = idx / WW, wl = idx - L * WW;
        loc[idx] = g_mask[(size_t)L * NW + wl];
    }
    __syncthreads();

    const int g = t / NW;            // group 0..6 (t < 1008)
    const int w = t - g * NW;

    for (int win = 0; win < NWIN; ++win) {
        const int cur = (win & 1) * (WB * WW), nxt = (WB * WW) - cur;
        if (win + 1 < NWIN) {        // prefetch next window (hidden behind greedy + OR)
#pragma unroll
            for (int k = 0; k < 9; k++) {
                int idx = t + k * 1024;
                int L = idx / WW, wl = idx - L * WW;
                loc[nxt + idx] =
                    g_mask[(size_t)((win + 1) * WB + L) * NW + (win + 1) * WW + wl];
            }
        }
        if (t == 0) {
            unsigned long long aw[WW], kw[WW];
#pragma unroll
            for (int wl = 0; wl < WW; wl++) {
                aw[wl] = ~remv[win * WW + wl];
                kw[wl] = 0;
            }
            int cnt = 0;
#pragma unroll
            for (int wl = 0; wl < WW; wl++) {
                unsigned long long avail = aw[wl];
                while (avail) {
                    int b = __ffsll((long long)avail) - 1;
                    int L = wl * 64 + b;
                    kw[wl] |= 1ull << b;
                    s_kept[cnt++] = L;
                    const unsigned long long* lp = &loc[cur + L * WW];
                    avail &= ~(lp[wl] | (1ull << b));
#pragma unroll
                    for (int w2 = 0; w2 < WW; w2++)
                        if (w2 > wl) aw[w2] &= ~lp[w2];
                }
            }
            s_cnt = cnt;
#pragma unroll
            for (int wl = 0; wl < WW; wl++) g_keepw[win * WW + wl] = kw[wl];
        }
        __syncthreads();
        const int cnt = s_cnt;
        if (g < 7 && w >= (win + 1) * WW && cnt > g) {
            unsigned long long acc = 0;
            for (int k = g; k < cnt; k += 7)
                acc |= g_mask[(size_t)(win * WB + s_kept[k]) * NW + w];
            if (acc) atomicOr(&remv[w], acc);
        }
        __syncthreads();
    }
}

// ---------------- finalize (separate kernel) ----------------
__global__ void k_final(float* __restrict__ out) {
    int r = blockIdx.x * blockDim.x + threadIdx.x;
    if (r >= N_BOX) return;
    int orig = g_sorder[r];
    float m = (float)((g_keepw[r >> 6] >> (r & 63)) & 1ull);
    float4 b = g_boxes[orig];
    out[4 * orig + 0] = b.x * m;
    out[4 * orig + 1] = b.y * m;
    out[4 * orig + 2] = b.z * m;
    out[4 * orig + 3] = b.w * m;
    out[55296 + orig] = m;
}

// ---------------- launcher ----------------
extern "C" void kernel_launch(void* const* d_in, const int* in_sizes, int n_in,
                              void* d_out, int out_size) {
    const float* feat   = (const float*)d_in[0];
    const int*   imgsz  = (const int*)d_in[1];
    const float* conv_w = (const float*)d_in[2];
    const float* conv_b = (const float*)d_in[3];
    const float* cls_w  = (const float*)d_in[4];
    const float* cls_b  = (const float*)d_in[5];
    const float* bbox_w = (const float*)d_in[6];
    const float* bbox_b = (const float*)d_in[7];
    float* out = (float*)d_out;

    cudaFuncSetAttribute(k_reduce, cudaFuncAttributeMaxDynamicSharedMemorySize,
                         2 * WB * WW * (int)sizeof(unsigned long long));

    k_conv<<<dim3(32, 8), 256>>>(feat, conv_w, conv_b);
    k_heads<<<dim3(32, 4), 256>>>(cls_w, bbox_w);
    k_prop<<<36, 256>>>(out, imgsz, cls_b, bbox_b);
    k_rank<<<dim3(36, 8), 256>>>();
    k_scatter<<<36, 256>>>();
    k_mask<<<2610, 256>>>();
    k_reduce<<<1, 1024, 2 * WB * WW * sizeof(unsigned long long)>>>();
    k_final<<<36, 256>>>(out);
}

// round 16
// speedup vs baseline: 1.1183x; 1.0183x over previous
#include <cuda_runtime.h>
#include <cstdint>

#define N_BOX 9216
#define NW 144            // 9216/64 mask words per row
#define NWIN 18           // 18 windows of 512 boxes (8 words) each

// ---------------- device scratch (no allocations allowed) ----------------
__device__ float g_x[512 * 1024];                      // conv output (relu'd)
__device__ float g_hpart[4 * 54 * 1024];               // head partial sums (4 c-chunks)
__device__ float4 g_boxes[N_BOX];                      // clipped proposals, original order
__device__ float4 g_sbox[N_BOX];                       // sorted boxes
__device__ float  g_sarea[N_BOX];
__device__ int    g_sorder[N_BOX];
__device__ int    g_rank[N_BOX];
__device__ unsigned long long g_keys[N_BOX];
__device__ unsigned long long g_mask[(size_t)N_BOX * NW];  // 10.6 MB suppression bitmask
__device__ unsigned long long g_keepw[NW];

// ---------------- 3x3 conv + bias + relu (R9 frozen — FFMA+LDS dual wall) ----------------
__global__ __launch_bounds__(256) void k_conv(const float* __restrict__ feat,
                                              const float* __restrict__ W,
                                              const float* __restrict__ B) {
    __shared__ float sf[8 * 222];    // 8 ch x (6 rows x 37)
    __shared__ float sw[16 * 72];    // 16 oc x 72 taps per chunk
    const int tid = threadIdx.x;
    const int oc0 = blockIdx.x * 16;
    const int y0 = blockIdx.y * 4;
    const int xg = tid & 7, rr = (tid >> 3) & 3, og = tid >> 5;
    const int x0 = xg * 4;

    for (int i = tid; i < 8 * 222; i += 256) sf[i] = 0.f;

    int fga[2], fsa[2];
    bool fv[2];
#pragma unroll
    for (int k = 0; k < 2; k++) {
        int idx = tid + k * 256;
        bool live = idx < 384;
        int cc = idx / 48, r6 = (idx >> 3) % 6, q = idx & 7;
        int gy = y0 + r6 - 1;
        fv[k] = live && ((unsigned)gy < 32u);
        fga[k] = cc * 1024 + gy * 32 + q * 4;
        fsa[k] = cc * 222 + r6 * 37 + 1 + q * 4;
    }
    int wga[5], wsa[5];
    bool wv[5];
#pragma unroll
    for (int k = 0; k < 5; k++) {
        int i = tid + k * 256;
        wv[k] = i < 1152;
        int o = i / 72, rem = i - o * 72;
        wga[k] = (oc0 + o) * 2304 + rem;
        wsa[k] = o * 72 + rem;
    }

    float4 pf[2];
    float pw[5];
#pragma unroll
    for (int k = 0; k < 2; k++)
        pf[k] = fv[k] ? *(const float4*)(feat + fga[k]) : make_float4(0.f, 0.f, 0.f, 0.f);
#pragma unroll
    for (int k = 0; k < 5; k++)
        pw[k] = wv[k] ? W[wga[k]] : 0.f;

    float acc[2][4];
#pragma unroll
    for (int a = 0; a < 2; a++)
#pragma unroll
        for (int b = 0; b < 4; b++) acc[a][b] = 0.f;

    __syncthreads();

    for (int c0 = 0; c0 < 256; c0 += 8) {
#pragma unroll
        for (int k = 0; k < 2; k++)
            if (fv[k]) {
                float* s = &sf[fsa[k]];
                s[0] = pf[k].x; s[1] = pf[k].y; s[2] = pf[k].z; s[3] = pf[k].w;
            }
#pragma unroll
        for (int k = 0; k < 5; k++)
            if (wv[k]) sw[wsa[k]] = pw[k];
        __syncthreads();

        if (c0 + 8 < 256) {
#pragma unroll
            for (int k = 0; k < 2; k++) {
                fga[k] += 8 * 1024;
                if (fv[k]) pf[k] = *(const float4*)(feat + fga[k]);
            }
#pragma unroll
            for (int k = 0; k < 5; k++) {
                wga[k] += 72;
                if (wv[k]) pw[k] = W[wga[k]];
            }
        }

#pragma unroll
        for (int cc = 0; cc < 8; cc++) {
            float f[3][6];
#pragma unroll
            for (int dy = 0; dy < 3; dy++)
#pragma unroll
                for (int dx = 0; dx < 6; dx++)
                    f[dy][dx] = sf[cc * 222 + (rr + dy) * 37 + x0 + dx];
#pragma unroll
            for (int o2 = 0; o2 < 2; o2++) {
                const float* wp = &sw[(og * 2 + o2) * 72 + cc * 9];
                float w0 = wp[0], w1 = wp[1], w2 = wp[2], w3 = wp[3], w4 = wp[4];
                float w5 = wp[5], w6 = wp[6], w7 = wp[7], w8 = wp[8];
#pragma unroll
                for (int p = 0; p < 4; p++) {
                    float s = acc[o2][p];
                    s += w0 * f[0][p]; s += w1 * f[0][p + 1]; s += w2 * f[0][p + 2];
                    s += w3 * f[1][p]; s += w4 * f[1][p + 1]; s += w5 * f[1][p + 2];
                    s += w6 * f[2][p]; s += w7 * f[2][p + 1]; s += w8 * f[2][p + 2];
                    acc[o2][p] = s;
                }
            }
        }
        __syncthreads();
    }

    const int y = y0 + rr;
#pragma unroll
    for (int o2 = 0; o2 < 2; o2++) {
        int oc = oc0 + og * 2 + o2;
        float b = B[oc];
#pragma unroll
        for (int p = 0; p < 4; p++) {
            float v = acc[o2][p] + b;
            g_x[oc * 1024 + y * 32 + x0 + p] = v > 0.f ? v : 0.f;
        }
    }
}

// ---------------- 1x1 heads (R9 frozen) ----------------
__global__ __launch_bounds__(256) void k_heads(const float* __restrict__ cw,
                                               const float* __restrict__ bw) {
    __shared__ float red[54][32];
    const int tid = threadIdx.x;
    const int lane = tid & 31, sub = tid >> 5;
    const int px = blockIdx.x * 32 + lane;
    const int q = blockIdx.y;

    float ac[18], ab[36];
#pragma unroll
    for (int o = 0; o < 18; o++) ac[o] = 0.f;
#pragma unroll
    for (int o = 0; o < 36; o++) ab[o] = 0.f;

    const int cbeg = q * 128 + sub * 16;
    for (int c = cbeg; c < cbeg + 16; c += 4) {
        float x0 = g_x[c * 1024 + px];
        float x1 = g_x[(c + 1) * 1024 + px];
        float x2 = g_x[(c + 2) * 1024 + px];
        float x3 = g_x[(c + 3) * 1024 + px];
#pragma unroll
        for (int o = 0; o < 18; o++) {
            float4 w = *(const float4*)(cw + o * 512 + c);
            ac[o] += w.x * x0 + w.y * x1 + w.z * x2 + w.w * x3;
        }
#pragma unroll
        for (int o = 0; o < 36; o++) {
            float4 w = *(const float4*)(bw + o * 512 + c);
            ab[o] += w.x * x0 + w.y * x1 + w.z * x2 + w.w * x3;
        }
    }

    for (int j = tid; j < 54 * 32; j += 256) (&red[0][0])[j] = 0.f;
    __syncthreads();
    for (int k = 0; k < 8; k++) {   // deterministic fixed-order sub accumulation
        if (sub == k) {
#pragma unroll
            for (int o = 0; o < 18; o++) red[o][lane] += ac[o];
#pragma unroll
            for (int o = 0; o < 36; o++) red[18 + o][lane] += ab[o];
        }
        __syncthreads();
    }
    for (int j = tid; j < 54 * 32; j += 256) {
        int o = j >> 5, p = j & 31;
        g_hpart[q * 55296 + o * 1024 + blockIdx.x * 32 + p] = red[o][p];
    }
}

// ---------------- head-sum helper: fixed-order 4-partial reduction ----------------
__device__ __forceinline__ float head_sum(int idx, float bias) {
    float v = bias;
    v += g_hpart[idx];
    v += g_hpart[55296 + idx];
    v += g_hpart[2 * 55296 + idx];
    v += g_hpart[3 * 55296 + idx];
    return v;
}

// ---------------- decode boxes + clip + keys + probs ----------------
__global__ void k_prop(float* __restrict__ out, const int* __restrict__ imgsz,
                       const float* __restrict__ cbv, const float* __restrict__ bbv) {
    int r = blockIdx.x * blockDim.x + threadIdx.x;
    if (r >= N_BOX) return;
    int isz = imgsz[0];
    float img = (float)isz;
    float strd = (float)(isz / 32);

    {   // probs: entries r and r+9216 of the 18432 prob outputs
        int o = r >> 10;
        float v = head_sum(r, cbv[o]);
        out[36864 + r] = 1.f / (1.f + expf(-v));
        int o2 = o + 9;
        float v2 = head_sum(r + 9216, cbv[o2]);
        out[36864 + 9216 + r] = 1.f / (1.f + expf(-v2));
    }

    int a = r >> 10, s = r & 1023;
    float logit = head_sum((2 * a + 1) * 1024 + s, cbv[2 * a + 1]);
    float score = 1.f / (1.f + expf(-logit));

    int c0 = r >> 8, s0 = (r & 255) << 2;
    float d[4];
#pragma unroll
    for (int k = 0; k < 4; k++)
        d[k] = head_sum((18 + c0) * 1024 + s0 + k, bbv[c0]);
    float dx = d[0], dyv = d[1], dw = d[2], dh = d[3];

    int sa = r / 9, aa = r - sa * 9;
    int ix = sa & 31, iy = sa >> 5;
    const float ratios[3] = {0.5f, 1.f, 2.f};
    const float scales[3] = {128.f, 256.f, 512.f};
    float ratio = ratios[aa / 3], scale = scales[aa % 3];
    float hr = sqrtf(ratio), wr = 1.f / hr;
    float w2 = rintf(0.5f * (wr * scale));
    float h2 = rintf(0.5f * (hr * scale));
    float shx = ix * strd, shy = iy * strd;
    float x1 = shx - w2, y1 = shy - h2, x2 = shx + w2, y2 = shy + h2;

    float w = x2 - x1, h = y2 - y1;
    float cx = x1 + 0.5f * w, cy = y1 + 0.5f * h;
    float pcx = dx * w + cx, pcy = dyv * h + cy;
    float pw = expf(dw) * w, ph = expf(dh) * h;
    float bx1 = pcx - 0.5f * pw, by1 = pcy - 0.5f * ph;
    float bx2 = pcx + 0.5f * pw, by2 = pcy + 0.5f * ph;
    bx1 = fminf(fmaxf(bx1, 0.f), img); by1 = fminf(fmaxf(by1, 0.f), img);
    bx2 = fminf(fmaxf(bx2, 0.f), img); by2 = fminf(fmaxf(by2, 0.f), img);

    g_boxes[r] = make_float4(bx1, by1, bx2, by2);
    unsigned int sb = __float_as_uint(score);
    g_keys[r] = ((unsigned long long)(~sb) << 32) | (unsigned int)r;
    g_rank[r] = 0;
}

// ---------------- rank by counting (R6 frozen optimum: grid (36,8), 4-way) ----------------
__global__ __launch_bounds__(256) void k_rank() {
    __shared__ unsigned long long sk[1152];
    const int tid = threadIdx.x;
    const int jbase = blockIdx.y * 1152;
    for (int j = tid; j < 1152; j += 256) sk[j] = g_keys[jbase + j];
    __syncthreads();
    const int i = blockIdx.x * 256 + tid;
    const unsigned long long ki = g_keys[i];
    int c0 = 0, c1 = 0, c2 = 0, c3 = 0;
#pragma unroll 4
    for (int j = 0; j < 1152; j += 4) {   // all lanes same addr -> LDS broadcast
        c0 += (sk[j]     < ki);
        c1 += (sk[j + 1] < ki);
        c2 += (sk[j + 2] < ki);
        c3 += (sk[j + 3] < ki);
    }
    atomicAdd(&g_rank[i], c0 + c1 + c2 + c3);
}

// ---------------- scatter into sorted order ----------------
__global__ void k_scatter() {
    int r = blockIdx.x * blockDim.x + threadIdx.x;
    if (r >= N_BOX) return;
    int rk = g_rank[r];
    g_sorder[rk] = r;
    float4 b = g_boxes[r];
    g_sbox[rk] = b;
    g_sarea[rk] = (b.z - b.x) * (b.w - b.y);
}

// ---------------- NMS bitmask: diag/off-diag specialized, 4 tiles per block ----------------
__global__ __launch_bounds__(256) void k_mask() {
    __shared__ float4 cbox[4][64];
    __shared__ float carea[4][64];
    const int t = threadIdx.x;
    const int sub = t >> 6, tt = t & 63;
    const int lin = blockIdx.x * 4 + sub;   // grid*4 == 10440 exactly

    int rb = (int)(NW + 0.5f - sqrtf((NW + 0.5f) * (NW + 0.5f) - 2.0f * (float)lin));
    while (rb > 0 && (rb * NW - rb * (rb - 1) / 2) > lin) rb--;
    while ((rb + 1) * NW - (rb + 1) * rb / 2 <= lin) rb++;
    const int cb = rb + (lin - (rb * NW - rb * (rb - 1) / 2));

    const int j0 = cb * 64;
    cbox[sub][tt] = g_sbox[j0 + tt];
    carea[sub][tt] = g_sarea[j0 + tt];
    __syncthreads();

    const int i = rb * 64 + tt;
    float4 bi = g_sbox[i];
    float ai = g_sarea[i];
    unsigned long long bits = 0;
    if (cb == rb) {
#pragma unroll 4
        for (int jj = 0; jj < 64; ++jj) {
            if (jj > tt) {
                float4 bj = cbox[sub][jj];
                float xx1 = fmaxf(bi.x, bj.x), yy1 = fmaxf(bi.y, bj.y);
                float xx2 = fminf(bi.z, bj.z), yy2 = fminf(bi.w, bj.w);
                float w = fmaxf(xx2 - xx1, 0.f), h = fmaxf(yy2 - yy1, 0.f);
                float inter = w * h;
                float iou = inter / (ai + carea[sub][jj] - inter + 1e-9f);
                if (iou > 0.3f) bits |= 1ull << jj;
            }
        }
    } else {
#pragma unroll 4
        for (int jj = 0; jj < 64; ++jj) {
            float4 bj = cbox[sub][jj];
            float xx1 = fmaxf(bi.x, bj.x), yy1 = fmaxf(bi.y, bj.y);
            float xx2 = fminf(bi.z, bj.z), yy2 = fminf(bi.w, bj.w);
            float w = fmaxf(xx2 - xx1, 0.f), h = fmaxf(yy2 - yy1, 0.f);
            float inter = w * h;
            float iou = inter / (ai + carea[sub][jj] - inter + 1e-9f);
            if (iou > 0.3f) bits |= 1ull << jj;
        }
    }
    g_mask[(size_t)i * NW + cb] = bits;
}

// ---------------- windowed greedy reduce: 18 iterations of 512 boxes (R12 frozen) ----------------
__global__ __launch_bounds__(1024) void k_reduce() {
    extern __shared__ unsigned long long loc[];     // [2][512][8] = 64 KB
    __shared__ unsigned long long remv[NW];
    __shared__ int s_kept[512];
    __shared__ int s_cnt;
    const int t = threadIdx.x;
    if (t < NW) remv[t] = 0;
#pragma unroll
    for (int k = 0; k < 4; k++) {                   // preload window 0 local words
        int idx = t + k * 1024;
        int L = idx >> 3, wl = idx & 7;
        loc[idx] = g_mask[(size_t)L * NW + wl];
    }
    __syncthreads();

    const int g = t / NW;            // group 0..6 (t < 1008)
    const int w = t - g * NW;

    for (int win = 0; win < NWIN; ++win) {
        const int cur = (win & 1) * 4096, nxt = 4096 - cur;
        if (win + 1 < NWIN) {        // prefetch next window (hidden behind greedy + OR)
#pragma unroll
            for (int k = 0; k < 4; k++) {
                int idx = t + k * 1024;
                int L = idx >> 3, wl = idx & 7;
                loc[nxt + idx] =
                    g_mask[(size_t)((win + 1) * 512 + L) * NW + (win + 1) * 8 + wl];
            }
        }
        if (t == 0) {
            unsigned long long aw[8], kw[8];
#pragma unroll
            for (int wl = 0; wl < 8; wl++) {
                aw[wl] = ~remv[win * 8 + wl];
                kw[wl] = 0;
            }
            int cnt = 0;
#pragma unroll
            for (int wl = 0; wl < 8; wl++) {
                unsigned long long avail = aw[wl];
                while (avail) {
                    int b = __ffsll((long long)avail) - 1;
                    int L = wl * 64 + b;
                    kw[wl] |= 1ull << b;
                    s_kept[cnt++] = L;
                    const unsigned long long* lp = &loc[cur + L * 8];
                    avail &= ~(lp[wl] | (1ull << b));
#pragma unroll
                    for (int w2 = 0; w2 < 8; w2++)
                        if (w2 > wl) aw[w2] &= ~lp[w2];
                }
            }
            s_cnt = cnt;
#pragma unroll
            for (int wl = 0; wl < 8; wl++) g_keepw[win * 8 + wl] = kw[wl];
        }
        __syncthreads();
        const int cnt = s_cnt;
        if (g < 7 && w >= (win + 1) * 8 && cnt > g) {
            unsigned long long acc = 0;
            for (int k = g; k < cnt; k += 7)
                acc |= g_mask[(size_t)(win * 512 + s_kept[k]) * NW + w];
            if (acc) atomicOr(&remv[w], acc);
        }
        __syncthreads();
    }
}

// ---------------- finalize (separate kernel) ----------------
__global__ void k_final(float* __restrict__ out) {
    int r = blockIdx.x * blockDim.x + threadIdx.x;
    if (r >= N_BOX) return;
    int orig = g_sorder[r];
    float m = (float)((g_keepw[r >> 6] >> (r & 63)) & 1ull);
    float4 b = g_boxes[orig];
    out[4 * orig + 0] = b.x * m;
    out[4 * orig + 1] = b.y * m;
    out[4 * orig + 2] = b.z * m;
    out[4 * orig + 3] = b.w * m;
    out[55296 + orig] = m;
}

// ---------------- launcher ----------------
extern "C" void kernel_launch(void* const* d_in, const int* in_sizes, int n_in,
                              void* d_out, int out_size) {
    const float* feat   = (const float*)d_in[0];
    const int*   imgsz  = (const int*)d_in[1];
    const float* conv_w = (const float*)d_in[2];
    const float* conv_b = (const float*)d_in[3];
    const float* cls_w  = (const float*)d_in[4];
    const float* cls_b  = (const float*)d_in[5];
    const float* bbox_w = (const float*)d_in[6];
    const float* bbox_b = (const float*)d_in[7];
    float* out = (float*)d_out;

    cudaFuncSetAttribute(k_reduce, cudaFuncAttributeMaxDynamicSharedMemorySize, 65536);

    k_conv<<<dim3(32, 8), 256>>>(feat, conv_w, conv_b);
    k_heads<<<dim3(32, 4), 256>>>(cls_w, bbox_w);
    k_prop<<<36, 256>>>(out, imgsz, cls_b, bbox_b);
    k_rank<<<dim3(36, 8), 256>>>();
    k_scatter<<<36, 256>>>();
    k_mask<<<2610, 256>>>();
    k_reduce<<<1, 1024, 65536>>>();
    k_final<<<36, 256>>>(out);
}